// round 3
// baseline (speedup 1.0000x reference)
#include <cuda_runtime.h>
#include <math.h>

// Problem constants (fixed by the dataset)
#define NN 50000
#define NE 800000
#define DH 128
#define NF_STRIDE 131   // 3 coords + 128 features
#define PAD 132         // padded row length for smem A tiles (bank-conflict avoidance, float4-aligned)

// ---------------------------------------------------------------------------
// Scratch (static __device__ arrays; allocation inside kernel_launch is banned)
// ---------------------------------------------------------------------------
__device__ float g_P1 [NN * DH];   // h @ We1[0:128]   + be1   (per-node, reused per edge via first)
__device__ float g_P2 [NN * DH];   // h @ We1[128:256]          (per-node, via second)
__device__ float g_Q  [NN * DH];   // h @ Wn1[0:128]   + bn1
__device__ float g_nbr[NN * DH];   // segment_sum(m, first)
__device__ float g_cs [NN * 3];    // segment_sum(coord_msg, first)
__device__ float g_cnt[NN];        // segment_sum(1, first)

__device__ __forceinline__ float silu_f(float x) {
    // x * sigmoid(x); fast-math variants: rel err ~1e-6, far under 1e-3 budget
    return x * __fdividef(1.0f, 1.0f + __expf(-x));
}

// ---------------------------------------------------------------------------
// Block-level 128x128x128 SGEMM:  C[128][128] += A[128][128] * B[128][128]
// A in smem row-major with PAD row stride; B in smem row-major (stride 128).
// 256 threads as 16x16, each computing an 8x8 register tile.
// ---------------------------------------------------------------------------
__device__ __forceinline__ void gemm128(const float* __restrict__ As,
                                        const float* __restrict__ Bs,
                                        float acc[8][8], int tx, int ty)
{
    const int row0 = ty * 8;
    const int col0 = tx * 8;
    #pragma unroll 2
    for (int k0 = 0; k0 < 128; k0 += 4) {
        float4 a4[8];
        #pragma unroll
        for (int r = 0; r < 8; ++r)
            a4[r] = *(const float4*)&As[(row0 + r) * PAD + k0];
        #pragma unroll
        for (int kk = 0; kk < 4; ++kk) {
            float4 b0 = *(const float4*)&Bs[(k0 + kk) * 128 + col0];
            float4 b1 = *(const float4*)&Bs[(k0 + kk) * 128 + col0 + 4];
            float bv[8];
            bv[0] = b0.x; bv[1] = b0.y; bv[2] = b0.z; bv[3] = b0.w;
            bv[4] = b1.x; bv[5] = b1.y; bv[6] = b1.z; bv[7] = b1.w;
            #pragma unroll
            for (int r = 0; r < 8; ++r) {
                float a = (kk == 0) ? a4[r].x : (kk == 1) ? a4[r].y
                        : (kk == 2) ? a4[r].z : a4[r].w;
                #pragma unroll
                for (int c = 0; c < 8; ++c)
                    acc[r][c] += a * bv[c];
            }
        }
    }
}

// ---------------------------------------------------------------------------
// Kernel 1: per-node precompute P1/P2/Q + zero accumulators
// grid = ceil(NN/128), block = 256, smem = (128*PAD + 128*128) floats
// ---------------------------------------------------------------------------
extern "C" __global__ void __launch_bounds__(256, 1)
k_pre(const float* __restrict__ nf,
      const float* __restrict__ We1, const float* __restrict__ be1,
      const float* __restrict__ Wn1, const float* __restrict__ bn1)
{
    extern __shared__ float sm[];
    float* As = sm;                 // [128][PAD]
    float* Ws = sm + 128 * PAD;     // [128][128]

    const int tid = threadIdx.x;
    const int tx = tid & 15, ty = tid >> 4;
    const int n0 = blockIdx.x * 128;

    // Load A = h tile (cols 3..130 of node_features); zero-pad rows past NN
    for (int idx = tid; idx < 128 * 128; idx += 256) {
        int r = idx >> 7, k = idx & 127;
        int n = n0 + r;
        As[r * PAD + k] = (n < NN) ? nf[n * NF_STRIDE + 3 + k] : 0.0f;
    }
    // Zero the atomic accumulators for this node range
    if (tid < 128) {
        int n = n0 + tid;
        if (n < NN) {
            g_cnt[n] = 0.0f;
            g_cs[n * 3 + 0] = 0.0f;
            g_cs[n * 3 + 1] = 0.0f;
            g_cs[n * 3 + 2] = 0.0f;
        }
    }
    for (int idx = tid; idx < 128 * 32; idx += 256) {
        int r = idx >> 5, c4 = (idx & 31) << 2;
        int n = n0 + r;
        if (n < NN)
            *(float4*)&g_nbr[n * DH + c4] = make_float4(0.f, 0.f, 0.f, 0.f);
    }

    #pragma unroll 1
    for (int w = 0; w < 3; ++w) {
        const float* Wsrc = (w == 0) ? We1
                          : (w == 1) ? (We1 + 128 * 128)   // We1 rows 128..255
                          : Wn1;                            // Wn1 rows 0..127
        __syncthreads();   // previous GEMM done reading Ws / As loads complete
        for (int idx = tid; idx < 128 * 32; idx += 256)
            *(float4*)&Ws[idx << 2] = *(const float4*)&Wsrc[idx << 2];
        __syncthreads();

        float acc[8][8];
        #pragma unroll
        for (int r = 0; r < 8; ++r)
            #pragma unroll
            for (int c = 0; c < 8; ++c) acc[r][c] = 0.0f;
        gemm128(As, Ws, acc, tx, ty);

        float* dst = (w == 0) ? g_P1 : (w == 1) ? g_P2 : g_Q;
        #pragma unroll
        for (int r = 0; r < 8; ++r) {
            int n = n0 + ty * 8 + r;
            if (n < NN) {
                #pragma unroll
                for (int c = 0; c < 8; ++c) {
                    float b = (w == 0) ? be1[tx * 8 + c]
                            : (w == 2) ? bn1[tx * 8 + c] : 0.0f;
                    dst[n * DH + tx * 8 + c] = acc[r][c] + b;
                }
            }
        }
    }
}

// ---------------------------------------------------------------------------
// Kernel 2: per-edge-tile fused MLP + atomic scatter
// grid = NE/128 = 6250 (exact), block = 256
// ---------------------------------------------------------------------------
extern "C" __global__ void __launch_bounds__(256, 1)
k_edge(const float* __restrict__ nf, const int* __restrict__ ei,
       const float* __restrict__ efeat,
       const float* __restrict__ We1,
       const float* __restrict__ We2, const float* __restrict__ be2,
       const float* __restrict__ Wc,  const float* __restrict__ bc)
{
    extern __shared__ float sm[];
    float* Z1   = sm;                     // [128][PAD]  z1 -> m1
    float* WB   = Z1   + 128 * PAD;       // [128][128]  We2
    float* EFs  = WB   + 128 * 128;       // [128][16]   edge features tile
    float* WEF  = EFs  + 128 * 16;        // [16][128]   We1 rows 257..272
    float* W256 = WEF  + 16 * 128;        // [128]       We1 row 256 (dist2)
    float* BE2  = W256 + 128;             // [128]
    float* WCs  = BE2  + 128;             // [128]
    float* sDX  = WCs  + 128;
    float* sDY  = sDX  + 128;
    float* sDZ  = sDY  + 128;
    float* sD2  = sDZ  + 128;
    float* Part = sD2  + 128;             // [128][16]  c_e partial sums
    int*   sI   = (int*)(Part + 128 * 16);  // [128]
    int*   sJ   = sI + 128;                 // [128]  (sI+sJ = 256 floats budget)

    const int tid = threadIdx.x;
    const int tx = tid & 15, ty = tid >> 4;
    const int e0 = blockIdx.x * 128;

    // --- Phase A: stage weights / per-edge metadata -----------------------
    for (int idx = tid; idx < 128 * 32; idx += 256)
        *(float4*)&WB[idx << 2] = *(const float4*)&We2[idx << 2];
    for (int idx = tid; idx < 16 * 32; idx += 256)
        *(float4*)&WEF[idx << 2] = *(const float4*)&We1[257 * 128 + (idx << 2)];
    if (tid < 128) {
        W256[tid] = We1[256 * 128 + tid];
        BE2[tid]  = be2[tid];
        WCs[tid]  = Wc[tid];
        int e = e0 + tid;
        int i = ei[e];
        int j = ei[NE + e];
        sI[tid] = i; sJ[tid] = j;
        float dx = nf[i * NF_STRIDE + 0] - nf[j * NF_STRIDE + 0];
        float dy = nf[i * NF_STRIDE + 1] - nf[j * NF_STRIDE + 1];
        float dz = nf[i * NF_STRIDE + 2] - nf[j * NF_STRIDE + 2];
        sDX[tid] = dx; sDY[tid] = dy; sDZ[tid] = dz;
        sD2[tid] = dx * dx + dy * dy + dz * dz;
    }
    for (int idx = tid; idx < 128 * 4; idx += 256)
        *(float4*)&EFs[idx << 2] = *(const float4*)&efeat[e0 * 16 + (idx << 2)];
    __syncthreads();

    // --- Phase B: m1 = silu(P1[i] + P2[j] + d2*w256 + ef@Wef) -------------
    // One warp per edge row -> P1/P2 gathers are fully coalesced 512B rows (L2-resident).
    for (int idx = tid; idx < 128 * 32; idx += 256) {
        int e  = idx >> 5;
        int c4 = (idx & 31) << 2;
        int i = sI[e], j = sJ[e];
        float4 z = *(const float4*)&g_P1[i * DH + c4];
        float4 q = *(const float4*)&g_P2[j * DH + c4];
        z.x += q.x; z.y += q.y; z.z += q.z; z.w += q.w;
        float d2 = sD2[e];
        float4 wv = *(const float4*)&W256[c4];
        z.x += d2 * wv.x; z.y += d2 * wv.y; z.z += d2 * wv.z; z.w += d2 * wv.w;
        #pragma unroll
        for (int k = 0; k < 16; ++k) {
            float ev = EFs[e * 16 + k];          // broadcast within warp
            float4 w = *(const float4*)&WEF[k * 128 + c4];
            z.x += ev * w.x; z.y += ev * w.y; z.z += ev * w.z; z.w += ev * w.w;
        }
        z.x = silu_f(z.x); z.y = silu_f(z.y); z.z = silu_f(z.z); z.w = silu_f(z.w);
        *(float4*)&Z1[e * PAD + c4] = z;
    }
    __syncthreads();

    // --- Phase C: m = silu(m1 @ We2 + be2) --------------------------------
    float acc[8][8];
    #pragma unroll
    for (int r = 0; r < 8; ++r)
        #pragma unroll
        for (int c = 0; c < 8; ++c) acc[r][c] = 0.0f;
    gemm128(Z1, WB, acc, tx, ty);
    #pragma unroll
    for (int r = 0; r < 8; ++r)
        #pragma unroll
        for (int c = 0; c < 8; ++c)
            acc[r][c] = silu_f(acc[r][c] + BE2[tx * 8 + c]);

    // --- Phase D: c_e = m @ Wc + bc, coord atomics ------------------------
    #pragma unroll
    for (int r = 0; r < 8; ++r) {
        float p = 0.0f;
        #pragma unroll
        for (int c = 0; c < 8; ++c)
            p += acc[r][c] * WCs[tx * 8 + c];
        Part[(ty * 8 + r) * 16 + tx] = p;
    }
    __syncthreads();
    if (tid < 128) {
        float ce = bc[0];
        #pragma unroll
        for (int t = 0; t < 16; ++t) ce += Part[tid * 16 + t];
        int i = sI[tid];
        atomicAdd(&g_cs[i * 3 + 0], sDX[tid] * ce);
        atomicAdd(&g_cs[i * 3 + 1], sDY[tid] * ce);
        atomicAdd(&g_cs[i * 3 + 2], sDZ[tid] * ce);
        atomicAdd(&g_cnt[i], 1.0f);
    }

    // --- Phase E: nbr_sum scatter -----------------------------------------
    #pragma unroll
    for (int r = 0; r < 8; ++r) {
        int i = sI[ty * 8 + r];
        float* dst = &g_nbr[i * DH + tx * 8];
        #pragma unroll
        for (int c = 0; c < 8; ++c)
            atomicAdd(dst + c, acc[r][c]);
    }
}

// ---------------------------------------------------------------------------
// Kernel 3: node update + packed output
// grid = ceil(NN/128), block = 256, smem = (128*PAD + 128*128) floats
// ---------------------------------------------------------------------------
extern "C" __global__ void __launch_bounds__(256, 1)
k_node(const float* __restrict__ nf,
       const float* __restrict__ Wn1,
       const float* __restrict__ Wn2, const float* __restrict__ bn2,
       float* __restrict__ out)
{
    extern __shared__ float sm[];
    float* As = sm;                 // [128][PAD]
    float* Ws = sm + 128 * PAD;     // [128][128]

    const int tid = threadIdx.x;
    const int tx = tid & 15, ty = tid >> 4;
    const int n0 = blockIdx.x * 128;

    // As = nbr_sum tile; Ws = Wn1 rows 128..255
    for (int idx = tid; idx < 128 * 32; idx += 256) {
        int r = idx >> 5, c4 = (idx & 31) << 2;
        int n = n0 + r;
        float4 v = (n < NN) ? *(const float4*)&g_nbr[n * DH + c4]
                            : make_float4(0.f, 0.f, 0.f, 0.f);
        *(float4*)&As[r * PAD + c4] = v;
    }
    for (int idx = tid; idx < 128 * 32; idx += 256)
        *(float4*)&Ws[idx << 2] = *(const float4*)&Wn1[128 * 128 + (idx << 2)];
    __syncthreads();

    float acc[8][8];
    #pragma unroll
    for (int r = 0; r < 8; ++r)
        #pragma unroll
        for (int c = 0; c < 8; ++c) acc[r][c] = 0.0f;
    gemm128(As, Ws, acc, tx, ty);

    // u = silu(acc + Q)   (Q already includes bn1)
    #pragma unroll
    for (int r = 0; r < 8; ++r) {
        int n = n0 + ty * 8 + r;
        if (n < NN) {
            float4 q0 = *(const float4*)&g_Q[n * DH + tx * 8];
            float4 q1 = *(const float4*)&g_Q[n * DH + tx * 8 + 4];
            acc[r][0] = silu_f(acc[r][0] + q0.x);
            acc[r][1] = silu_f(acc[r][1] + q0.y);
            acc[r][2] = silu_f(acc[r][2] + q0.z);
            acc[r][3] = silu_f(acc[r][3] + q0.w);
            acc[r][4] = silu_f(acc[r][4] + q1.x);
            acc[r][5] = silu_f(acc[r][5] + q1.y);
            acc[r][6] = silu_f(acc[r][6] + q1.z);
            acc[r][7] = silu_f(acc[r][7] + q1.w);
        }
    }
    __syncthreads();   // all threads finished reading As/Ws of GEMM 1

    // Store U into As; load Wn2
    #pragma unroll
    for (int r = 0; r < 8; ++r)
        #pragma unroll
        for (int c = 0; c < 8; ++c)
            As[(ty * 8 + r) * PAD + tx * 8 + c] = acc[r][c];
    for (int idx = tid; idx < 128 * 32; idx += 256)
        *(float4*)&Ws[idx << 2] = *(const float4*)&Wn2[idx << 2];
    __syncthreads();

    float acc2[8][8];
    #pragma unroll
    for (int r = 0; r < 8; ++r)
        #pragma unroll
        for (int c = 0; c < 8; ++c) acc2[r][c] = 0.0f;
    gemm128(As, Ws, acc2, tx, ty);

    // Write node output (cols 3..130 of packed rows)
    #pragma unroll
    for (int r = 0; r < 8; ++r) {
        int n = n0 + ty * 8 + r;
        if (n < NN) {
            #pragma unroll
            for (int c = 0; c < 8; ++c)
                out[n * NF_STRIDE + 3 + tx * 8 + c] = acc2[r][c] + bn2[tx * 8 + c];
        }
    }
    // Coord epilogue
    if (tid < 128) {
        int n = n0 + tid;
        if (n < NN) {
            float cnt = g_cnt[n];
            float inv = 1.0f / fmaxf(cnt, 1.0f);
            out[n * NF_STRIDE + 0] = nf[n * NF_STRIDE + 0] + g_cs[n * 3 + 0] * inv;
            out[n * NF_STRIDE + 1] = nf[n * NF_STRIDE + 1] + g_cs[n * 3 + 1] * inv;
            out[n * NF_STRIDE + 2] = nf[n * NF_STRIDE + 2] + g_cs[n * 3 + 2] * inv;
        }
    }
}

// ---------------------------------------------------------------------------
// Launch
// ---------------------------------------------------------------------------
extern "C" void kernel_launch(void* const* d_in, const int* in_sizes, int n_in,
                              void* d_out, int out_size)
{
    const float* nf    = (const float*)d_in[0];   // node_features (50000, 131)
    const int*   ei    = (const int*)  d_in[1];   // edge_index (2, 800000) int32
    const float* efeat = (const float*)d_in[2];   // edge_features (800000, 16)
    const float* We1   = (const float*)d_in[3];   // (273, 128)
    const float* be1   = (const float*)d_in[4];   // (128,)
    const float* We2   = (const float*)d_in[5];   // (128, 128)
    const float* be2   = (const float*)d_in[6];   // (128,)
    const float* Wc    = (const float*)d_in[7];   // (128, 1)
    const float* bc    = (const float*)d_in[8];   // (1,)
    const float* Wn1   = (const float*)d_in[9];   // (256, 128)
    const float* bn1   = (const float*)d_in[10];  // (128,)
    const float* Wn2   = (const float*)d_in[11];  // (128, 128)
    const float* bn2   = (const float*)d_in[12];  // (128,)
    float* out = (float*)d_out;

    const int sm_node = (128 * PAD + 128 * 128) * (int)sizeof(float);   // 133120 B
    // Z1 + WB + EFs + WEF + (W256,BE2,WCs,sDX,sDY,sDZ,sD2) + Part + sI/sJ(256 ints)
    const int sm_edge = (128 * PAD + 128 * 128 + 128 * 16 + 16 * 128 +
                         128 * 7 + 128 * 16 + 256) * (int)sizeof(float); // 162304 B

    cudaFuncSetAttribute(k_pre,  cudaFuncAttributeMaxDynamicSharedMemorySize, sm_node);
    cudaFuncSetAttribute(k_edge, cudaFuncAttributeMaxDynamicSharedMemorySize, sm_edge);
    cudaFuncSetAttribute(k_node, cudaFuncAttributeMaxDynamicSharedMemorySize, sm_node);

    const int nblk_node = (NN + 127) / 128;   // 391
    const int nblk_edge = NE / 128;           // 6250 (exact)

    k_pre <<<nblk_node, 256, sm_node>>>(nf, We1, be1, Wn1, bn1);
    k_edge<<<nblk_edge, 256, sm_edge>>>(nf, ei, efeat, We1, We2, be2, Wc, bc);
    k_node<<<nblk_node, 256, sm_node>>>(nf, Wn1, Wn2, bn2, out);
}

// round 4
// speedup vs baseline: 1.1664x; 1.1664x over previous
#include <cuda_runtime.h>
#include <math.h>

// Problem constants (fixed by the dataset)
#define NN 50000
#define NE 800000
#define DH 128
#define NF_STRIDE 131   // 3 coords + 128 features
#define PAD 132         // padded row length for smem A tiles

// ---------------------------------------------------------------------------
// Scratch (static __device__ arrays; allocation inside kernel_launch is banned)
// ---------------------------------------------------------------------------
__device__ float g_P1 [NN * DH];   // h @ We1[0:128]   + be1
__device__ float g_P2 [NN * DH];   // h @ We1[128:256]
__device__ float g_Q  [NN * DH];   // h @ Wn1[0:128]   + bn1
__device__ float g_nbr[NN * DH];   // segment_sum(m, first)
__device__ float g_cs [NN * 3];    // segment_sum(coord_msg, first)
__device__ float g_cnt[NN];        // segment_sum(1, first)

__device__ __forceinline__ float silu_f(float x) {
    return x * __fdividef(1.0f, 1.0f + __expf(-x));
}

__device__ __forceinline__ void red_v4(float* dst, float a, float b, float c, float d) {
    asm volatile("red.global.add.v4.f32 [%0], {%1,%2,%3,%4};"
                 :: "l"(dst), "f"(a), "f"(b), "f"(c), "f"(d) : "memory");
}

// ---------------------------------------------------------------------------
// Block-level 256x128x128 SGEMM: C[256][128] += A[256][128] * B[128][128]
// As row-major stride PAD; Bs row-major stride 128.
// 256 threads as 16(tx) x 16(ty); thread computes 16 rows x 8 cols.
// ~2 FMA per smem byte (vs 1 for the 8x8 tile) -> smem BW no longer binding.
// ---------------------------------------------------------------------------
__device__ __forceinline__ void gemm256(const float* __restrict__ As,
                                        const float* __restrict__ Bs,
                                        float acc[16][8], int tx, int ty)
{
    const int col0 = tx * 8;
    const int row0 = ty * 16;
    #pragma unroll 1
    for (int k0 = 0; k0 < 128; k0 += 4) {
        float4 b4[4][2];
        #pragma unroll
        for (int kk = 0; kk < 4; ++kk) {
            b4[kk][0] = *(const float4*)&Bs[(k0 + kk) * 128 + col0];
            b4[kk][1] = *(const float4*)&Bs[(k0 + kk) * 128 + col0 + 4];
        }
        #pragma unroll
        for (int half = 0; half < 2; ++half) {
            float4 a4[8];
            #pragma unroll
            for (int r = 0; r < 8; ++r)
                a4[r] = *(const float4*)&As[(row0 + half * 8 + r) * PAD + k0];
            #pragma unroll
            for (int kk = 0; kk < 4; ++kk) {
                float bv[8];
                bv[0] = b4[kk][0].x; bv[1] = b4[kk][0].y;
                bv[2] = b4[kk][0].z; bv[3] = b4[kk][0].w;
                bv[4] = b4[kk][1].x; bv[5] = b4[kk][1].y;
                bv[6] = b4[kk][1].z; bv[7] = b4[kk][1].w;
                #pragma unroll
                for (int r = 0; r < 8; ++r) {
                    float a = (kk == 0) ? a4[r].x : (kk == 1) ? a4[r].y
                            : (kk == 2) ? a4[r].z : a4[r].w;
                    #pragma unroll
                    for (int c = 0; c < 8; ++c)
                        acc[half * 8 + r][c] += a * bv[c];
                }
            }
        }
    }
}

// ---------------------------------------------------------------------------
// Kernel 1: per-node precompute P1/P2/Q + zero accumulators
// grid = ceil(NN/256) = 196, block = 256
// ---------------------------------------------------------------------------
extern "C" __global__ void __launch_bounds__(256, 1)
k_pre(const float* __restrict__ nf,
      const float* __restrict__ We1, const float* __restrict__ be1,
      const float* __restrict__ Wn1, const float* __restrict__ bn1)
{
    extern __shared__ float sm[];
    float* As = sm;                 // [256][PAD]
    float* Ws = sm + 256 * PAD;     // [128][128]

    const int tid = threadIdx.x;
    const int tx = tid & 15, ty = tid >> 4;
    const int n0 = blockIdx.x * 256;

    // Load A = h tile (cols 3..130); scalar loads (rows not 16B aligned)
    for (int idx = tid; idx < 256 * 128; idx += 256) {
        int r = idx >> 7, k = idx & 127;
        int n = n0 + r;
        As[r * PAD + k] = (n < NN) ? nf[n * NF_STRIDE + 3 + k] : 0.0f;
    }
    // Zero the atomic accumulators for this node range
    {
        int n = n0 + tid;
        if (n < NN) {
            g_cnt[n] = 0.0f;
            g_cs[n * 3 + 0] = 0.0f;
            g_cs[n * 3 + 1] = 0.0f;
            g_cs[n * 3 + 2] = 0.0f;
        }
    }
    for (int idx = tid; idx < 256 * 32; idx += 256) {
        int r = idx >> 5, c4 = (idx & 31) << 2;
        int n = n0 + r;
        if (n < NN)
            *(float4*)&g_nbr[n * DH + c4] = make_float4(0.f, 0.f, 0.f, 0.f);
    }

    #pragma unroll 1
    for (int w = 0; w < 3; ++w) {
        const float* Wsrc = (w == 0) ? We1
                          : (w == 1) ? (We1 + 128 * 128)
                          : Wn1;
        __syncthreads();
        for (int idx = tid; idx < 128 * 32; idx += 256)
            *(float4*)&Ws[idx << 2] = *(const float4*)&Wsrc[idx << 2];
        __syncthreads();

        float acc[16][8];
        #pragma unroll
        for (int r = 0; r < 16; ++r)
            #pragma unroll
            for (int c = 0; c < 8; ++c) acc[r][c] = 0.0f;
        gemm256(As, Ws, acc, tx, ty);

        float* dst = (w == 0) ? g_P1 : (w == 1) ? g_P2 : g_Q;
        #pragma unroll
        for (int r = 0; r < 16; ++r) {
            int n = n0 + ty * 16 + r;
            if (n < NN) {
                #pragma unroll
                for (int c = 0; c < 8; ++c) {
                    float b = (w == 0) ? be1[tx * 8 + c]
                            : (w == 2) ? bn1[tx * 8 + c] : 0.0f;
                    dst[n * DH + tx * 8 + c] = acc[r][c] + b;
                }
            }
        }
    }
}

// ---------------------------------------------------------------------------
// Kernel 2: per-edge-tile fused MLP + vector-red scatter
// grid = NE/256 = 3125 (exact), block = 256
// ---------------------------------------------------------------------------
extern "C" __global__ void __launch_bounds__(256, 1)
k_edge(const float* __restrict__ nf, const int* __restrict__ ei,
       const float* __restrict__ efeat,
       const float* __restrict__ We1,
       const float* __restrict__ We2, const float* __restrict__ be2,
       const float* __restrict__ Wc,  const float* __restrict__ bc)
{
    extern __shared__ float sm[];
    float* Z1   = sm;                     // [256][PAD]  z1 -> m1           33792 f
    float* WB   = Z1   + 256 * PAD;       // [128][128]  We2                16384 f
    float* EFs  = WB   + 128 * 128;       // [256][16]  edge feats / Part   4096 f (union)
    float* WEF  = EFs  + 256 * 16;        // [16][128]  We1 rows 257..272   2048 f
    float* W256 = WEF  + 16 * 128;        // [128]      We1 row 256
    float* BE2  = W256 + 128;             // [128]
    float* WCs  = BE2  + 128;             // [128]
    float* sDX  = WCs  + 128;             // [256]
    float* sDY  = sDX  + 256;             // [256]
    float* sDZ  = sDY  + 256;             // [256]
    int*   sI   = (int*)(sDZ + 256);      // [256]
    int*   sJ   = sI + 256;               // [256]
    float* Part = EFs;                    // [256][16]  (reuse after Phase B)

    const int tid = threadIdx.x;
    const int tx = tid & 15, ty = tid >> 4;
    const int e0 = blockIdx.x * 256;

    // --- Phase A: stage weights / per-edge metadata -----------------------
    for (int idx = tid; idx < 128 * 32; idx += 256)
        *(float4*)&WB[idx << 2] = *(const float4*)&We2[idx << 2];
    for (int idx = tid; idx < 16 * 32; idx += 256)
        *(float4*)&WEF[idx << 2] = *(const float4*)&We1[257 * 128 + (idx << 2)];
    if (tid < 128) {
        W256[tid] = We1[256 * 128 + tid];
        BE2[tid]  = be2[tid];
        WCs[tid]  = Wc[tid];
    }
    {
        int e = e0 + tid;
        int i = ei[e];
        int j = ei[NE + e];
        sI[tid] = i; sJ[tid] = j;
        float dx = nf[i * NF_STRIDE + 0] - nf[j * NF_STRIDE + 0];
        float dy = nf[i * NF_STRIDE + 1] - nf[j * NF_STRIDE + 1];
        float dz = nf[i * NF_STRIDE + 2] - nf[j * NF_STRIDE + 2];
        sDX[tid] = dx; sDY[tid] = dy; sDZ[tid] = dz;
    }
    for (int idx = tid; idx < 256 * 4; idx += 256)
        *(float4*)&EFs[idx << 2] = *(const float4*)&efeat[e0 * 16 + (idx << 2)];
    __syncthreads();

    // --- Phase B: m1 = silu(P1[i] + P2[j] + d2*w256 + ef@Wef) -------------
    // Warp-per-edge-row: P1/P2 gathers are coalesced 512B rows (L2-resident).
    for (int idx = tid; idx < 256 * 32; idx += 256) {
        int e  = idx >> 5;
        int c4 = (idx & 31) << 2;
        int i = sI[e], j = sJ[e];
        float4 z = *(const float4*)&g_P1[i * DH + c4];
        float4 q = *(const float4*)&g_P2[j * DH + c4];
        z.x += q.x; z.y += q.y; z.z += q.z; z.w += q.w;
        float dx = sDX[e], dy = sDY[e], dz = sDZ[e];
        float d2 = dx * dx + dy * dy + dz * dz;
        float4 wv = *(const float4*)&W256[c4];
        z.x += d2 * wv.x; z.y += d2 * wv.y; z.z += d2 * wv.z; z.w += d2 * wv.w;
        #pragma unroll
        for (int k = 0; k < 16; ++k) {
            float ev = EFs[e * 16 + k];          // broadcast within warp
            float4 w = *(const float4*)&WEF[k * 128 + c4];
            z.x += ev * w.x; z.y += ev * w.y; z.z += ev * w.z; z.w += ev * w.w;
        }
        z.x = silu_f(z.x); z.y = silu_f(z.y); z.z = silu_f(z.z); z.w = silu_f(z.w);
        *(float4*)&Z1[e * PAD + c4] = z;
    }
    __syncthreads();

    // --- Phase C: m = silu(m1 @ We2 + be2) --------------------------------
    float acc[16][8];
    #pragma unroll
    for (int r = 0; r < 16; ++r)
        #pragma unroll
        for (int c = 0; c < 8; ++c) acc[r][c] = 0.0f;
    gemm256(Z1, WB, acc, tx, ty);
    #pragma unroll
    for (int r = 0; r < 16; ++r)
        #pragma unroll
        for (int c = 0; c < 8; ++c)
            acc[r][c] = silu_f(acc[r][c] + BE2[tx * 8 + c]);

    // --- Phase D: c_e = m @ Wc + bc, coord atomics ------------------------
    // (Part aliases EFs; EFs dead after Phase B, sync above covers the WAR.)
    #pragma unroll
    for (int r = 0; r < 16; ++r) {
        float p = 0.0f;
        #pragma unroll
        for (int c = 0; c < 8; ++c)
            p += acc[r][c] * WCs[tx * 8 + c];
        Part[(ty * 16 + r) * 16 + tx] = p;
    }
    __syncthreads();
    {
        float ce = bc[0];
        #pragma unroll
        for (int t = 0; t < 16; ++t) ce += Part[tid * 16 + t];
        int i = sI[tid];
        atomicAdd(&g_cs[i * 3 + 0], sDX[tid] * ce);
        atomicAdd(&g_cs[i * 3 + 1], sDY[tid] * ce);
        atomicAdd(&g_cs[i * 3 + 2], sDZ[tid] * ce);
        atomicAdd(&g_cnt[i], 1.0f);
    }

    // --- Phase E: nbr_sum scatter (vector red: 4 floats per instruction) --
    #pragma unroll
    for (int r = 0; r < 16; ++r) {
        int i = sI[ty * 16 + r];
        float* dst = &g_nbr[i * DH + tx * 8];
        red_v4(dst,     acc[r][0], acc[r][1], acc[r][2], acc[r][3]);
        red_v4(dst + 4, acc[r][4], acc[r][5], acc[r][6], acc[r][7]);
    }
}

// ---------------------------------------------------------------------------
// Kernel 3: node update + packed output
// grid = ceil(NN/256) = 196, block = 256
// ---------------------------------------------------------------------------
extern "C" __global__ void __launch_bounds__(256, 1)
k_node(const float* __restrict__ nf,
       const float* __restrict__ Wn1,
       const float* __restrict__ Wn2, const float* __restrict__ bn2,
       float* __restrict__ out)
{
    extern __shared__ float sm[];
    float* As = sm;                 // [256][PAD]
    float* Ws = sm + 256 * PAD;     // [128][128]

    const int tid = threadIdx.x;
    const int tx = tid & 15, ty = tid >> 4;
    const int n0 = blockIdx.x * 256;

    // As = nbr_sum tile; Ws = Wn1 rows 128..255
    for (int idx = tid; idx < 256 * 32; idx += 256) {
        int r = idx >> 5, c4 = (idx & 31) << 2;
        int n = n0 + r;
        float4 v = (n < NN) ? *(const float4*)&g_nbr[n * DH + c4]
                            : make_float4(0.f, 0.f, 0.f, 0.f);
        *(float4*)&As[r * PAD + c4] = v;
    }
    for (int idx = tid; idx < 128 * 32; idx += 256)
        *(float4*)&Ws[idx << 2] = *(const float4*)&Wn1[128 * 128 + (idx << 2)];
    __syncthreads();

    float acc[16][8];
    #pragma unroll
    for (int r = 0; r < 16; ++r)
        #pragma unroll
        for (int c = 0; c < 8; ++c) acc[r][c] = 0.0f;
    gemm256(As, Ws, acc, tx, ty);

    // u = silu(acc + Q)   (Q already includes bn1)
    #pragma unroll
    for (int r = 0; r < 16; ++r) {
        int n = n0 + ty * 16 + r;
        if (n < NN) {
            float4 q0 = *(const float4*)&g_Q[n * DH + tx * 8];
            float4 q1 = *(const float4*)&g_Q[n * DH + tx * 8 + 4];
            acc[r][0] = silu_f(acc[r][0] + q0.x);
            acc[r][1] = silu_f(acc[r][1] + q0.y);
            acc[r][2] = silu_f(acc[r][2] + q0.z);
            acc[r][3] = silu_f(acc[r][3] + q0.w);
            acc[r][4] = silu_f(acc[r][4] + q1.x);
            acc[r][5] = silu_f(acc[r][5] + q1.y);
            acc[r][6] = silu_f(acc[r][6] + q1.z);
            acc[r][7] = silu_f(acc[r][7] + q1.w);
        }
    }
    __syncthreads();   // GEMM 1 reads of As/Ws complete

    // Store U into As; load Wn2
    #pragma unroll
    for (int r = 0; r < 16; ++r)
        #pragma unroll
        for (int c = 0; c < 8; ++c)
            As[(ty * 16 + r) * PAD + tx * 8 + c] = acc[r][c];
    for (int idx = tid; idx < 128 * 32; idx += 256)
        *(float4*)&Ws[idx << 2] = *(const float4*)&Wn2[idx << 2];
    __syncthreads();

    float acc2[16][8];
    #pragma unroll
    for (int r = 0; r < 16; ++r)
        #pragma unroll
        for (int c = 0; c < 8; ++c) acc2[r][c] = 0.0f;
    gemm256(As, Ws, acc2, tx, ty);

    // Write node output (cols 3..130 of packed rows)
    #pragma unroll
    for (int r = 0; r < 16; ++r) {
        int n = n0 + ty * 16 + r;
        if (n < NN) {
            #pragma unroll
            for (int c = 0; c < 8; ++c)
                out[n * NF_STRIDE + 3 + tx * 8 + c] = acc2[r][c] + bn2[tx * 8 + c];
        }
    }
    // Coord epilogue (one node per thread)
    {
        int n = n0 + tid;
        if (n < NN) {
            float cnt = g_cnt[n];
            float inv = 1.0f / fmaxf(cnt, 1.0f);
            out[n * NF_STRIDE + 0] = nf[n * NF_STRIDE + 0] + g_cs[n * 3 + 0] * inv;
            out[n * NF_STRIDE + 1] = nf[n * NF_STRIDE + 1] + g_cs[n * 3 + 1] * inv;
            out[n * NF_STRIDE + 2] = nf[n * NF_STRIDE + 2] + g_cs[n * 3 + 2] * inv;
        }
    }
}

// ---------------------------------------------------------------------------
// Launch
// ---------------------------------------------------------------------------
extern "C" void kernel_launch(void* const* d_in, const int* in_sizes, int n_in,
                              void* d_out, int out_size)
{
    const float* nf    = (const float*)d_in[0];   // node_features (50000, 131)
    const int*   ei    = (const int*)  d_in[1];   // edge_index (2, 800000) int32
    const float* efeat = (const float*)d_in[2];   // edge_features (800000, 16)
    const float* We1   = (const float*)d_in[3];   // (273, 128)
    const float* be1   = (const float*)d_in[4];   // (128,)
    const float* We2   = (const float*)d_in[5];   // (128, 128)
    const float* be2   = (const float*)d_in[6];   // (128,)
    const float* Wc    = (const float*)d_in[7];   // (128, 1)
    const float* bc    = (const float*)d_in[8];   // (1,)
    const float* Wn1   = (const float*)d_in[9];   // (256, 128)
    const float* bn1   = (const float*)d_in[10];  // (128,)
    const float* Wn2   = (const float*)d_in[11];  // (128, 128)
    const float* bn2   = (const float*)d_in[12];  // (128,)
    float* out = (float*)d_out;

    const int sm_node = (256 * PAD + 128 * 128) * (int)sizeof(float);   // 200704 B
    // Z1 + WB + EFs/Part + WEF + W256/BE2/WCs + sDX/sDY/sDZ + sI/sJ
    const int sm_edge = (256 * PAD + 128 * 128 + 256 * 16 + 16 * 128 +
                         128 * 3 + 256 * 3 + 512) * (int)sizeof(float); // 231936 B

    cudaFuncSetAttribute(k_pre,  cudaFuncAttributeMaxDynamicSharedMemorySize, sm_node);
    cudaFuncSetAttribute(k_edge, cudaFuncAttributeMaxDynamicSharedMemorySize, sm_edge);
    cudaFuncSetAttribute(k_node, cudaFuncAttributeMaxDynamicSharedMemorySize, sm_node);

    const int nblk_node = (NN + 255) / 256;   // 196
    const int nblk_edge = NE / 256;           // 3125 (exact)

    k_pre <<<nblk_node, 256, sm_node>>>(nf, We1, be1, Wn1, bn1);
    k_edge<<<nblk_edge, 256, sm_edge>>>(nf, ei, efeat, We1, We2, be2, Wc, bc);
    k_node<<<nblk_node, 256, sm_node>>>(nf, Wn1, Wn2, bn2, out);
}